// round 10
// baseline (speedup 1.0000x reference)
#include <cuda_runtime.h>
#include <cuda_fp16.h>
#include <cstdint>

// LinearInterpolator: trilinear sampling of 300k points into a (16,112,224,160) fp32 volume.
// Strategy: transpose to channel-last fp16 scratch [x][y][z][16] (32 B/voxel), keeping the
// scratch L2-resident: streaming (.cs) reads of the fp32 volume + evict_last v8 scratch
// writes (ptxas requires v8.b32 width for evict_last stores). Gather then hits L2.
//
// d_in[0] = vert (1, 300000, 3) fp32
// d_in[1] = vol  (1, 16, 112, 224, 160) fp32
// d_out   = (1, 300000, 16) fp32

#define D1 112
#define D2 224
#define D3 160
#define NCH 16
#define EPS_F 1e-5f

#define NVOX   (D1 * D2 * D3)             // 4,014,080 (even)

// channel-last fp16 scratch: [voxel][16 halves] = 32 B/voxel -> 128.5 MB
__device__ __align__(32) uint32_t g_vt[(size_t)NVOX * 8];

// ---------------------------------------------------------------------------
// Memory helpers
// ---------------------------------------------------------------------------
// scratch write: 256-bit, bias to stay in L2 (evict_last requires v8.b32 width)
__device__ __forceinline__ void stg256_el(uint32_t* p, const uint32_t r[8])
{
    asm volatile("st.global.L2::evict_last.v8.b32 [%0], {%1,%2,%3,%4,%5,%6,%7,%8};"
                 :: "l"(p),
                    "r"(r[0]), "r"(r[1]), "r"(r[2]), "r"(r[3]),
                    "r"(r[4]), "r"(r[5]), "r"(r[6]), "r"(r[7])
                 : "memory");
}

// gather corner read: 256-bit
__device__ __forceinline__ void ldg256(const uint32_t* p, uint32_t r[8])
{
    asm volatile("ld.global.nc.v8.b32 {%0,%1,%2,%3,%4,%5,%6,%7}, [%8];"
                 : "=r"(r[0]), "=r"(r[1]), "=r"(r[2]), "=r"(r[3]),
                   "=r"(r[4]), "=r"(r[5]), "=r"(r[6]), "=r"(r[7])
                 : "l"(p));
}

// ---------------------------------------------------------------------------
// Transpose: vol[c][v] (fp32) -> g_vt[v][c] (fp16), 2 voxels per thread.
// Reads: __ldcs streaming float2 per channel. Writes: one evict_last v8 per voxel.
// ---------------------------------------------------------------------------
__global__ __launch_bounds__(256)
void transpose_kernel(const float* __restrict__ vol)
{
    int v2 = blockIdx.x * blockDim.x + threadIdx.x;
    if (v2 >= NVOX / 2) return;
    size_t v = (size_t)v2 * 2;

    float a[NCH], b[NCH];      // channel values for voxel v and v+1
    #pragma unroll
    for (int c = 0; c < NCH; c++) {
        float2 ab = __ldcs((const float2*)(vol + (size_t)c * NVOX + v));
        a[c] = ab.x;
        b[c] = ab.y;
    }

    uint32_t wa[8], wb[8];
    #pragma unroll
    for (int i = 0; i < 8; i++) {
        __half2 ha = __floats2half2_rn(a[2 * i], a[2 * i + 1]);
        __half2 hb = __floats2half2_rn(b[2 * i], b[2 * i + 1]);
        wa[i] = *(const uint32_t*)&ha;
        wb[i] = *(const uint32_t*)&hb;
    }

    uint32_t* dst = g_vt + v * 8;
    stg256_el(dst,     wa);
    stg256_el(dst + 8, wb);
}

// ---------------------------------------------------------------------------
// Gather: 1 thread per point. 8 corners x one 256-bit load (32 B = 16 halves).
// All fp32 lerp math; output via streaming (__stcs) float4 stores.
// ---------------------------------------------------------------------------
__global__ __launch_bounds__(128)
void gather_kernel(const float* __restrict__ vert,
                   float* __restrict__ out,
                   int npts)
{
    int p = blockIdx.x * blockDim.x + threadIdx.x;
    if (p >= npts) return;

    float vx = vert[p * 3 + 0];
    float vy = vert[p * 3 + 1];
    float vz = vert[p * 3 + 2];

    vx = fminf(fmaxf(vx, EPS_F), (float)(D1 - 1) - EPS_F);
    vy = fminf(fmaxf(vy, EPS_F), (float)(D2 - 1) - EPS_F);
    vz = fminf(fmaxf(vz, EPS_F), (float)(D3 - 1) - EPS_F);

    float fx = floorf(vx);
    float fy = floorf(vy);
    float fz = floorf(vz);

    float ux = vx - fx;
    float uy = vy - fy;
    float uz = vz - fz;

    int x0 = (int)fx;
    int y0 = (int)fy;
    int z0 = (int)fz;

    // base in uint32 units: voxel * 8
    const uint32_t* __restrict__ V =
        g_vt + (((size_t)x0 * (D2 * D3) + (size_t)y0 * D3 + z0) << 3);

    // corner offsets in uint32 units
    const int OZ = 8;                 // z+1
    const int OY = D3 * 8;            // y+1
    const int OX = D2 * D3 * 8;       // x+1

    // 8 independent 32 B loads, front-batched for MLP
    uint32_t q000[8], q001[8], q010[8], q011[8];
    uint32_t q100[8], q101[8], q110[8], q111[8];
    ldg256(V,                 q000);
    ldg256(V + OZ,            q001);
    ldg256(V + OY,            q010);
    ldg256(V + OY + OZ,       q011);
    ldg256(V + OX,            q100);
    ldg256(V + OX + OZ,       q101);
    ldg256(V + OX + OY,       q110);
    ldg256(V + OX + OY + OZ,  q111);

    float r[16];

    #pragma unroll
    for (int i = 0; i < 8; i++) {
        float2 f000 = __half22float2(*(const __half2*)&q000[i]);
        float2 f001 = __half22float2(*(const __half2*)&q001[i]);
        float2 f010 = __half22float2(*(const __half2*)&q010[i]);
        float2 f011 = __half22float2(*(const __half2*)&q011[i]);
        float2 f100 = __half22float2(*(const __half2*)&q100[i]);
        float2 f101 = __half22float2(*(const __half2*)&q101[i]);
        float2 f110 = __half22float2(*(const __half2*)&q110[i]);
        float2 f111 = __half22float2(*(const __half2*)&q111[i]);

        float a00x = fmaf(ux, f100.x - f000.x, f000.x);
        float a01x = fmaf(ux, f101.x - f001.x, f001.x);
        float a10x = fmaf(ux, f110.x - f010.x, f010.x);
        float a11x = fmaf(ux, f111.x - f011.x, f011.x);
        float a00y = fmaf(ux, f100.y - f000.y, f000.y);
        float a01y = fmaf(ux, f101.y - f001.y, f001.y);
        float a10y = fmaf(ux, f110.y - f010.y, f010.y);
        float a11y = fmaf(ux, f111.y - f011.y, f011.y);

        float b0x = fmaf(uy, a10x - a00x, a00x);
        float b1x = fmaf(uy, a11x - a01x, a01x);
        float b0y = fmaf(uy, a10y - a00y, a00y);
        float b1y = fmaf(uy, a11y - a01y, a01y);

        r[2 * i]     = fmaf(uz, b1x - b0x, b0x);
        r[2 * i + 1] = fmaf(uz, b1y - b0y, b0y);
    }

    float4* o = (float4*)(out + (size_t)p * 16);
    __stcs(o,     make_float4(r[0],  r[1],  r[2],  r[3]));
    __stcs(o + 1, make_float4(r[4],  r[5],  r[6],  r[7]));
    __stcs(o + 2, make_float4(r[8],  r[9],  r[10], r[11]));
    __stcs(o + 3, make_float4(r[12], r[13], r[14], r[15]));
}

extern "C" void kernel_launch(void* const* d_in, const int* in_sizes, int n_in,
                              void* d_out, int out_size)
{
    const float* vert = (const float*)d_in[0];
    const float* vol  = (const float*)d_in[1];
    float* out = (float*)d_out;

    int npts = in_sizes[0] / 3;   // 300000

    {
        int threads = 256;
        int blocks = (NVOX / 2 + threads - 1) / threads;
        transpose_kernel<<<blocks, threads>>>(vol);
    }
    {
        int threads = 128;
        int blocks = (npts + threads - 1) / threads;
        gather_kernel<<<blocks, threads>>>(vert, out, npts);
    }
}

// round 11
// speedup vs baseline: 1.0011x; 1.0011x over previous
#include <cuda_runtime.h>
#include <cuda_fp16.h>
#include <cstdint>

// LinearInterpolator: trilinear sampling of 300k points into a (16,112,224,160) fp32 volume.
// Strategy: transpose to channel-last fp16 scratch [x][y][z][16] (32 B/voxel), keeping the
// scratch L2-resident: streaming (.cs) reads of the fp32 volume + evict_last v8 scratch
// writes (ptxas requires v8.b32 width for evict_last stores). Gather then hits L2.
//
// d_in[0] = vert (1, 300000, 3) fp32
// d_in[1] = vol  (1, 16, 112, 224, 160) fp32
// d_out   = (1, 300000, 16) fp32

#define D1 112
#define D2 224
#define D3 160
#define NCH 16
#define EPS_F 1e-5f

#define NVOX   (D1 * D2 * D3)             // 4,014,080 (even)

// channel-last fp16 scratch: [voxel][16 halves] = 32 B/voxel -> 128.5 MB
__device__ __align__(32) uint32_t g_vt[(size_t)NVOX * 8];

// ---------------------------------------------------------------------------
// Memory helpers
// ---------------------------------------------------------------------------
// scratch write: 256-bit, bias to stay in L2 (evict_last requires v8.b32 width)
__device__ __forceinline__ void stg256_el(uint32_t* p, const uint32_t r[8])
{
    asm volatile("st.global.L2::evict_last.v8.b32 [%0], {%1,%2,%3,%4,%5,%6,%7,%8};"
                 :: "l"(p),
                    "r"(r[0]), "r"(r[1]), "r"(r[2]), "r"(r[3]),
                    "r"(r[4]), "r"(r[5]), "r"(r[6]), "r"(r[7])
                 : "memory");
}

// gather corner read: 256-bit
__device__ __forceinline__ void ldg256(const uint32_t* p, uint32_t r[8])
{
    asm volatile("ld.global.nc.v8.b32 {%0,%1,%2,%3,%4,%5,%6,%7}, [%8];"
                 : "=r"(r[0]), "=r"(r[1]), "=r"(r[2]), "=r"(r[3]),
                   "=r"(r[4]), "=r"(r[5]), "=r"(r[6]), "=r"(r[7])
                 : "l"(p));
}

// ---------------------------------------------------------------------------
// Transpose: vol[c][v] (fp32) -> g_vt[v][c] (fp16), 2 voxels per thread.
// Reads: __ldcs streaming float2 per channel. Writes: one evict_last v8 per voxel.
// ---------------------------------------------------------------------------
__global__ __launch_bounds__(256)
void transpose_kernel(const float* __restrict__ vol)
{
    int v2 = blockIdx.x * blockDim.x + threadIdx.x;
    if (v2 >= NVOX / 2) return;
    size_t v = (size_t)v2 * 2;

    float a[NCH], b[NCH];      // channel values for voxel v and v+1
    #pragma unroll
    for (int c = 0; c < NCH; c++) {
        float2 ab = __ldcs((const float2*)(vol + (size_t)c * NVOX + v));
        a[c] = ab.x;
        b[c] = ab.y;
    }

    uint32_t wa[8], wb[8];
    #pragma unroll
    for (int i = 0; i < 8; i++) {
        __half2 ha = __floats2half2_rn(a[2 * i], a[2 * i + 1]);
        __half2 hb = __floats2half2_rn(b[2 * i], b[2 * i + 1]);
        wa[i] = *(const uint32_t*)&ha;
        wb[i] = *(const uint32_t*)&hb;
    }

    uint32_t* dst = g_vt + v * 8;
    stg256_el(dst,     wa);
    stg256_el(dst + 8, wb);
}

// ---------------------------------------------------------------------------
// Gather: 1 thread per point. 8 corners x one 256-bit load (32 B = 16 halves).
// All fp32 lerp math; output via streaming (__stcs) float4 stores.
// ---------------------------------------------------------------------------
__global__ __launch_bounds__(128)
void gather_kernel(const float* __restrict__ vert,
                   float* __restrict__ out,
                   int npts)
{
    int p = blockIdx.x * blockDim.x + threadIdx.x;
    if (p >= npts) return;

    float vx = vert[p * 3 + 0];
    float vy = vert[p * 3 + 1];
    float vz = vert[p * 3 + 2];

    vx = fminf(fmaxf(vx, EPS_F), (float)(D1 - 1) - EPS_F);
    vy = fminf(fmaxf(vy, EPS_F), (float)(D2 - 1) - EPS_F);
    vz = fminf(fmaxf(vz, EPS_F), (float)(D3 - 1) - EPS_F);

    float fx = floorf(vx);
    float fy = floorf(vy);
    float fz = floorf(vz);

    float ux = vx - fx;
    float uy = vy - fy;
    float uz = vz - fz;

    int x0 = (int)fx;
    int y0 = (int)fy;
    int z0 = (int)fz;

    // base in uint32 units: voxel * 8
    const uint32_t* __restrict__ V =
        g_vt + (((size_t)x0 * (D2 * D3) + (size_t)y0 * D3 + z0) << 3);

    // corner offsets in uint32 units
    const int OZ = 8;                 // z+1
    const int OY = D3 * 8;            // y+1
    const int OX = D2 * D3 * 8;       // x+1

    // 8 independent 32 B loads, front-batched for MLP
    uint32_t q000[8], q001[8], q010[8], q011[8];
    uint32_t q100[8], q101[8], q110[8], q111[8];
    ldg256(V,                 q000);
    ldg256(V + OZ,            q001);
    ldg256(V + OY,            q010);
    ldg256(V + OY + OZ,       q011);
    ldg256(V + OX,            q100);
    ldg256(V + OX + OZ,       q101);
    ldg256(V + OX + OY,       q110);
    ldg256(V + OX + OY + OZ,  q111);

    float r[16];

    #pragma unroll
    for (int i = 0; i < 8; i++) {
        float2 f000 = __half22float2(*(const __half2*)&q000[i]);
        float2 f001 = __half22float2(*(const __half2*)&q001[i]);
        float2 f010 = __half22float2(*(const __half2*)&q010[i]);
        float2 f011 = __half22float2(*(const __half2*)&q011[i]);
        float2 f100 = __half22float2(*(const __half2*)&q100[i]);
        float2 f101 = __half22float2(*(const __half2*)&q101[i]);
        float2 f110 = __half22float2(*(const __half2*)&q110[i]);
        float2 f111 = __half22float2(*(const __half2*)&q111[i]);

        float a00x = fmaf(ux, f100.x - f000.x, f000.x);
        float a01x = fmaf(ux, f101.x - f001.x, f001.x);
        float a10x = fmaf(ux, f110.x - f010.x, f010.x);
        float a11x = fmaf(ux, f111.x - f011.x, f011.x);
        float a00y = fmaf(ux, f100.y - f000.y, f000.y);
        float a01y = fmaf(ux, f101.y - f001.y, f001.y);
        float a10y = fmaf(ux, f110.y - f010.y, f010.y);
        float a11y = fmaf(ux, f111.y - f011.y, f011.y);

        float b0x = fmaf(uy, a10x - a00x, a00x);
        float b1x = fmaf(uy, a11x - a01x, a01x);
        float b0y = fmaf(uy, a10y - a00y, a00y);
        float b1y = fmaf(uy, a11y - a01y, a01y);

        r[2 * i]     = fmaf(uz, b1x - b0x, b0x);
        r[2 * i + 1] = fmaf(uz, b1y - b0y, b0y);
    }

    float4* o = (float4*)(out + (size_t)p * 16);
    __stcs(o,     make_float4(r[0],  r[1],  r[2],  r[3]));
    __stcs(o + 1, make_float4(r[4],  r[5],  r[6],  r[7]));
    __stcs(o + 2, make_float4(r[8],  r[9],  r[10], r[11]));
    __stcs(o + 3, make_float4(r[12], r[13], r[14], r[15]));
}

extern "C" void kernel_launch(void* const* d_in, const int* in_sizes, int n_in,
                              void* d_out, int out_size)
{
    const float* vert = (const float*)d_in[0];
    const float* vol  = (const float*)d_in[1];
    float* out = (float*)d_out;

    int npts = in_sizes[0] / 3;   // 300000

    {
        int threads = 256;
        int blocks = (NVOX / 2 + threads - 1) / threads;
        transpose_kernel<<<blocks, threads>>>(vol);
    }
    {
        int threads = 128;
        int blocks = (npts + threads - 1) / threads;
        gather_kernel<<<blocks, threads>>>(vert, out, npts);
    }
}

// round 12
// speedup vs baseline: 1.0041x; 1.0030x over previous
#include <cuda_runtime.h>
#include <cuda_fp16.h>
#include <cstdint>

// LinearInterpolator: trilinear sampling of 300k points into a (16,112,224,160) fp32 volume.
// Strategy: transpose to channel-last fp16 scratch [x][y][z][16] (32 B/voxel), keeping the
// scratch L2-resident: streaming (.cs) reads of the fp32 volume + evict_last v8 scratch
// writes (ptxas requires v8.b32 width for evict_last stores). Gather then hits L2.
//
// d_in[0] = vert (1, 300000, 3) fp32
// d_in[1] = vol  (1, 16, 112, 224, 160) fp32
// d_out   = (1, 300000, 16) fp32

#define D1 112
#define D2 224
#define D3 160
#define NCH 16
#define EPS_F 1e-5f

#define NVOX   (D1 * D2 * D3)             // 4,014,080 (even)

// channel-last fp16 scratch: [voxel][16 halves] = 32 B/voxel -> 128.5 MB
__device__ __align__(32) uint32_t g_vt[(size_t)NVOX * 8];

// ---------------------------------------------------------------------------
// Memory helpers
// ---------------------------------------------------------------------------
// scratch write: 256-bit, bias to stay in L2 (evict_last requires v8.b32 width)
__device__ __forceinline__ void stg256_el(uint32_t* p, const uint32_t r[8])
{
    asm volatile("st.global.L2::evict_last.v8.b32 [%0], {%1,%2,%3,%4,%5,%6,%7,%8};"
                 :: "l"(p),
                    "r"(r[0]), "r"(r[1]), "r"(r[2]), "r"(r[3]),
                    "r"(r[4]), "r"(r[5]), "r"(r[6]), "r"(r[7])
                 : "memory");
}

// gather corner read: 256-bit
__device__ __forceinline__ void ldg256(const uint32_t* p, uint32_t r[8])
{
    asm volatile("ld.global.nc.v8.b32 {%0,%1,%2,%3,%4,%5,%6,%7}, [%8];"
                 : "=r"(r[0]), "=r"(r[1]), "=r"(r[2]), "=r"(r[3]),
                   "=r"(r[4]), "=r"(r[5]), "=r"(r[6]), "=r"(r[7])
                 : "l"(p));
}

// ---------------------------------------------------------------------------
// Transpose: vol[c][v] (fp32) -> g_vt[v][c] (fp16), 2 voxels per thread.
// Reads: __ldcs streaming float2 per channel. Writes: one evict_last v8 per voxel.
// ---------------------------------------------------------------------------
__global__ __launch_bounds__(256)
void transpose_kernel(const float* __restrict__ vol)
{
    int v2 = blockIdx.x * blockDim.x + threadIdx.x;
    if (v2 >= NVOX / 2) return;
    size_t v = (size_t)v2 * 2;

    float a[NCH], b[NCH];      // channel values for voxel v and v+1
    #pragma unroll
    for (int c = 0; c < NCH; c++) {
        float2 ab = __ldcs((const float2*)(vol + (size_t)c * NVOX + v));
        a[c] = ab.x;
        b[c] = ab.y;
    }

    uint32_t wa[8], wb[8];
    #pragma unroll
    for (int i = 0; i < 8; i++) {
        __half2 ha = __floats2half2_rn(a[2 * i], a[2 * i + 1]);
        __half2 hb = __floats2half2_rn(b[2 * i], b[2 * i + 1]);
        wa[i] = *(const uint32_t*)&ha;
        wb[i] = *(const uint32_t*)&hb;
    }

    uint32_t* dst = g_vt + v * 8;
    stg256_el(dst,     wa);
    stg256_el(dst + 8, wb);
}

// ---------------------------------------------------------------------------
// Gather: 1 thread per point. 8 corners x one 256-bit load (32 B = 16 halves).
// All fp32 lerp math; output via streaming (__stcs) float4 stores.
// ---------------------------------------------------------------------------
__global__ __launch_bounds__(128)
void gather_kernel(const float* __restrict__ vert,
                   float* __restrict__ out,
                   int npts)
{
    int p = blockIdx.x * blockDim.x + threadIdx.x;
    if (p >= npts) return;

    float vx = vert[p * 3 + 0];
    float vy = vert[p * 3 + 1];
    float vz = vert[p * 3 + 2];

    vx = fminf(fmaxf(vx, EPS_F), (float)(D1 - 1) - EPS_F);
    vy = fminf(fmaxf(vy, EPS_F), (float)(D2 - 1) - EPS_F);
    vz = fminf(fmaxf(vz, EPS_F), (float)(D3 - 1) - EPS_F);

    float fx = floorf(vx);
    float fy = floorf(vy);
    float fz = floorf(vz);

    float ux = vx - fx;
    float uy = vy - fy;
    float uz = vz - fz;

    int x0 = (int)fx;
    int y0 = (int)fy;
    int z0 = (int)fz;

    // base in uint32 units: voxel * 8
    const uint32_t* __restrict__ V =
        g_vt + (((size_t)x0 * (D2 * D3) + (size_t)y0 * D3 + z0) << 3);

    // corner offsets in uint32 units
    const int OZ = 8;                 // z+1
    const int OY = D3 * 8;            // y+1
    const int OX = D2 * D3 * 8;       // x+1

    // 8 independent 32 B loads, front-batched for MLP
    uint32_t q000[8], q001[8], q010[8], q011[8];
    uint32_t q100[8], q101[8], q110[8], q111[8];
    ldg256(V,                 q000);
    ldg256(V + OZ,            q001);
    ldg256(V + OY,            q010);
    ldg256(V + OY + OZ,       q011);
    ldg256(V + OX,            q100);
    ldg256(V + OX + OZ,       q101);
    ldg256(V + OX + OY,       q110);
    ldg256(V + OX + OY + OZ,  q111);

    float r[16];

    #pragma unroll
    for (int i = 0; i < 8; i++) {
        float2 f000 = __half22float2(*(const __half2*)&q000[i]);
        float2 f001 = __half22float2(*(const __half2*)&q001[i]);
        float2 f010 = __half22float2(*(const __half2*)&q010[i]);
        float2 f011 = __half22float2(*(const __half2*)&q011[i]);
        float2 f100 = __half22float2(*(const __half2*)&q100[i]);
        float2 f101 = __half22float2(*(const __half2*)&q101[i]);
        float2 f110 = __half22float2(*(const __half2*)&q110[i]);
        float2 f111 = __half22float2(*(const __half2*)&q111[i]);

        float a00x = fmaf(ux, f100.x - f000.x, f000.x);
        float a01x = fmaf(ux, f101.x - f001.x, f001.x);
        float a10x = fmaf(ux, f110.x - f010.x, f010.x);
        float a11x = fmaf(ux, f111.x - f011.x, f011.x);
        float a00y = fmaf(ux, f100.y - f000.y, f000.y);
        float a01y = fmaf(ux, f101.y - f001.y, f001.y);
        float a10y = fmaf(ux, f110.y - f010.y, f010.y);
        float a11y = fmaf(ux, f111.y - f011.y, f011.y);

        float b0x = fmaf(uy, a10x - a00x, a00x);
        float b1x = fmaf(uy, a11x - a01x, a01x);
        float b0y = fmaf(uy, a10y - a00y, a00y);
        float b1y = fmaf(uy, a11y - a01y, a01y);

        r[2 * i]     = fmaf(uz, b1x - b0x, b0x);
        r[2 * i + 1] = fmaf(uz, b1y - b0y, b0y);
    }

    float4* o = (float4*)(out + (size_t)p * 16);
    __stcs(o,     make_float4(r[0],  r[1],  r[2],  r[3]));
    __stcs(o + 1, make_float4(r[4],  r[5],  r[6],  r[7]));
    __stcs(o + 2, make_float4(r[8],  r[9],  r[10], r[11]));
    __stcs(o + 3, make_float4(r[12], r[13], r[14], r[15]));
}

extern "C" void kernel_launch(void* const* d_in, const int* in_sizes, int n_in,
                              void* d_out, int out_size)
{
    const float* vert = (const float*)d_in[0];
    const float* vol  = (const float*)d_in[1];
    float* out = (float*)d_out;

    int npts = in_sizes[0] / 3;   // 300000

    {
        int threads = 256;
        int blocks = (NVOX / 2 + threads - 1) / threads;
        transpose_kernel<<<blocks, threads>>>(vol);
    }
    {
        int threads = 128;
        int blocks = (npts + threads - 1) / threads;
        gather_kernel<<<blocks, threads>>>(vert, out, npts);
    }
}